// round 6
// baseline (speedup 1.0000x reference)
#include <cuda_runtime.h>
#include <cuda_fp16.h>

// SegmentationLoss: ce(ignore=255, mean over valid) + 0.5 * dice
// pred [4,172,256,256] f32, target [4,256,256] i32 -> scalar f32
//
// Strategy: single DRAM pass over pred. Each thread owns one pixel,
// streams its 172 channel logits (coalesced), computes exp + running sum,
// stashes exp(x) as fp16 in shared (88KB tile -> 2 blocks/SM). Second
// (smem-only) pass does per-channel union sums via warp shuffles.
// Class-indexed stats (inter/counts) via shared atomics scattered by target.
// Global accumulators live in __device__ scratch (no allocations).

#define NC   172
#define HW   65536
#define NB   4
#define NPIX (NB * HW)          // 262144
#define TPB  256
#define NBLK (NPIX / TPB)       // 1024
#define IGN  255
#define EPSF 1e-7f

__device__ float g_union[NC];
__device__ float g_inter[NC];
__device__ float g_counts[NC];
__device__ float g_nll;
__device__ float g_valid;

__global__ void seg_zero() {
    int t = threadIdx.x;
    if (t < NC) { g_union[t] = 0.f; g_inter[t] = 0.f; g_counts[t] = 0.f; }
    if (t == NC) { g_nll = 0.f; g_valid = 0.f; }
}

extern __shared__ unsigned char smem_raw[];

__global__ __launch_bounds__(TPB, 2)
void seg_main(const float* __restrict__ pred, const int* __restrict__ target) {
    // shared layout:
    //   tile   : NC*TPB fp16 (exp stash, per-thread column -> conflict free)
    //   usum   : 8*NC f32 (per-warp per-channel union partials)
    //   inter_s: NC f32, cnt_s: NC f32 (target-scattered, shared atomics)
    //   red    : 16 f32 (nll / valid per-warp partials)
    __half* tile   = (__half*)smem_raw;
    float*  usum   = (float*)(smem_raw + (size_t)NC * TPB * sizeof(__half));
    float*  inter_s = usum + 8 * NC;
    float*  cnt_s   = inter_s + NC;
    float*  red     = cnt_s + NC;

    const int tid  = threadIdx.x;
    const int warp = tid >> 5;
    const int lane = tid & 31;

    for (int i = tid; i < NC; i += TPB) { inter_s[i] = 0.f; cnt_s[i] = 0.f; }
    __syncthreads();

    const int pix0 = blockIdx.x * TPB;          // 65536 % 256 == 0 -> never crosses batch
    const int b    = pix0 / HW;
    const int hw   = pix0 - b * HW;
    const float* base = pred + (size_t)b * NC * HW + hw + tid;

    const int  tgt   = target[pix0 + tid];
    const bool valid = (tgt != IGN);

    // ---- pass 1: stream DRAM, exp, sum, stash e as fp16 ----
    float s = 0.f, xt = 0.f;
    #pragma unroll 8
    for (int c = 0; c < NC; c++) {
        float x = __ldg(base + (size_t)c * HW);
        float e = __expf(x);
        s += e;
        tile[c * TPB + tid] = __float2half_rn(e);
        if (c == tgt) xt = x;
    }
    const float inv_s = 1.f / s;
    float nll = valid ? (__logf(s) - xt) : 0.f;
    float vv  = valid ? 1.f : 0.f;

    if (valid) {
        float pt = __expf(xt) * inv_s;          // p at target (fp32 path, exact)
        atomicAdd(&inter_s[tgt], pt);
        atomicAdd(&cnt_s[tgt], 1.f);
    }

    // block-reduce nll & valid count
    #pragma unroll
    for (int o = 16; o; o >>= 1) {
        nll += __shfl_xor_sync(0xffffffffu, nll, o);
        vv  += __shfl_xor_sync(0xffffffffu, vv,  o);
    }
    if (lane == 0) { red[warp] = nll; red[8 + warp] = vv; }

    // ---- pass 2: per-channel union = sum_p e[c,p]/s[p] (smem + shuffles only) ----
    #pragma unroll 2
    for (int c = 0; c < NC; c++) {
        float pv = __half2float(tile[c * TPB + tid]) * inv_s;
        #pragma unroll
        for (int o = 16; o; o >>= 1) pv += __shfl_xor_sync(0xffffffffu, pv, o);
        if (lane == 0) usum[warp * NC + c] = pv;
    }
    __syncthreads();

    // ---- fold block partials into global accumulators ----
    if (tid < NC) {
        float u = 0.f;
        #pragma unroll
        for (int w = 0; w < 8; w++) u += usum[w * NC + tid];
        atomicAdd(&g_union[tid], u);
        float iv = inter_s[tid];
        if (iv != 0.f) atomicAdd(&g_inter[tid], iv);
        float cv = cnt_s[tid];
        if (cv != 0.f) atomicAdd(&g_counts[tid], cv);
    } else if (tid == NC) {
        float n = 0.f, v = 0.f;
        #pragma unroll
        for (int w = 0; w < 8; w++) { n += red[w]; v += red[8 + w]; }
        atomicAdd(&g_nll, n);
        atomicAdd(&g_valid, v);
    }
}

__global__ void seg_final(float* __restrict__ out) {
    __shared__ float sh_d[8], sh_n[8];
    const int tid  = threadIdx.x;   // 256
    const int warp = tid >> 5;
    const int lane = tid & 31;

    float d = 0.f, n = 0.f;
    if (tid < NC) {
        float uni = g_union[tid] + g_counts[tid];
        if (uni > 0.f) {
            d = (2.f * g_inter[tid] + EPSF) / (uni + EPSF);
            n = 1.f;
        }
    }
    #pragma unroll
    for (int o = 16; o; o >>= 1) {
        d += __shfl_xor_sync(0xffffffffu, d, o);
        n += __shfl_xor_sync(0xffffffffu, n, o);
    }
    if (lane == 0) { sh_d[warp] = d; sh_n[warp] = n; }
    __syncthreads();

    if (tid == 0) {
        float dt = 0.f, nt = 0.f;
        #pragma unroll
        for (int w = 0; w < 8; w++) { dt += sh_d[w]; nt += sh_n[w]; }
        float ce   = g_nll / fmaxf(g_valid, 1.f);
        float dice = (nt > 0.f) ? (1.f - dt / fmaxf(nt, 1.f)) : 0.f;
        out[0] = ce + 0.5f * dice;
    }
}

extern "C" void kernel_launch(void* const* d_in, const int* in_sizes, int n_in,
                              void* d_out, int out_size) {
    const float* pred   = (const float*)d_in[0];
    const int*   target = (const int*)d_in[1];
    float*       out    = (float*)d_out;

    const size_t smem = (size_t)NC * TPB * sizeof(__half)
                      + (size_t)(8 * NC + NC + NC + 16) * sizeof(float); // 95008 B
    cudaFuncSetAttribute(seg_main, cudaFuncAttributeMaxDynamicSharedMemorySize, (int)smem);

    seg_zero<<<1, 256>>>();
    seg_main<<<NBLK, TPB, smem>>>(pred, target);
    seg_final<<<1, 256>>>(out);
}

// round 7
// speedup vs baseline: 1.0018x; 1.0018x over previous
#include <cuda_runtime.h>
#include <cuda_fp16.h>

// SegmentationLoss: ce(ignore=255, mean over valid) + 0.5 * dice
// pred [4,172,256,256] f32, target [4,256,256] i32 -> scalar f32
//
// Strategy: single DRAM pass over pred. Each thread owns one pixel,
// streams its 172 channel logits (coalesced), computes exp + running sum,
// stashes exp(x) as fp16 in shared (88KB tile -> 2 blocks/SM). Second
// (smem-only) pass does per-channel union sums via warp shuffles.
// Class-indexed stats (inter/counts) via shared atomics scattered by target.
// Global accumulators live in __device__ scratch (no allocations).

#define NC   172
#define HW   65536
#define NB   4
#define NPIX (NB * HW)          // 262144
#define TPB  256
#define NBLK (NPIX / TPB)       // 1024
#define IGN  255
#define EPSF 1e-7f

__device__ float g_union[NC];
__device__ float g_inter[NC];
__device__ float g_counts[NC];
__device__ float g_nll;
__device__ float g_valid;

__global__ void seg_zero() {
    int t = threadIdx.x;
    if (t < NC) { g_union[t] = 0.f; g_inter[t] = 0.f; g_counts[t] = 0.f; }
    if (t == NC) { g_nll = 0.f; g_valid = 0.f; }
}

extern __shared__ unsigned char smem_raw[];

__global__ __launch_bounds__(TPB, 2)
void seg_main(const float* __restrict__ pred, const int* __restrict__ target) {
    // shared layout:
    //   tile   : NC*TPB fp16 (exp stash, per-thread column -> conflict free)
    //   usum   : 8*NC f32 (per-warp per-channel union partials)
    //   inter_s: NC f32, cnt_s: NC f32 (target-scattered, shared atomics)
    //   red    : 16 f32 (nll / valid per-warp partials)
    __half* tile   = (__half*)smem_raw;
    float*  usum   = (float*)(smem_raw + (size_t)NC * TPB * sizeof(__half));
    float*  inter_s = usum + 8 * NC;
    float*  cnt_s   = inter_s + NC;
    float*  red     = cnt_s + NC;

    const int tid  = threadIdx.x;
    const int warp = tid >> 5;
    const int lane = tid & 31;

    for (int i = tid; i < NC; i += TPB) { inter_s[i] = 0.f; cnt_s[i] = 0.f; }
    __syncthreads();

    const int pix0 = blockIdx.x * TPB;          // 65536 % 256 == 0 -> never crosses batch
    const int b    = pix0 / HW;
    const int hw   = pix0 - b * HW;
    const float* base = pred + (size_t)b * NC * HW + hw + tid;

    const int  tgt   = target[pix0 + tid];
    const bool valid = (tgt != IGN);

    // ---- pass 1: stream DRAM, exp, sum, stash e as fp16 ----
    float s = 0.f, xt = 0.f;
    #pragma unroll 8
    for (int c = 0; c < NC; c++) {
        float x = __ldg(base + (size_t)c * HW);
        float e = __expf(x);
        s += e;
        tile[c * TPB + tid] = __float2half_rn(e);
        if (c == tgt) xt = x;
    }
    const float inv_s = 1.f / s;
    float nll = valid ? (__logf(s) - xt) : 0.f;
    float vv  = valid ? 1.f : 0.f;

    if (valid) {
        float pt = __expf(xt) * inv_s;          // p at target (fp32 path, exact)
        atomicAdd(&inter_s[tgt], pt);
        atomicAdd(&cnt_s[tgt], 1.f);
    }

    // block-reduce nll & valid count
    #pragma unroll
    for (int o = 16; o; o >>= 1) {
        nll += __shfl_xor_sync(0xffffffffu, nll, o);
        vv  += __shfl_xor_sync(0xffffffffu, vv,  o);
    }
    if (lane == 0) { red[warp] = nll; red[8 + warp] = vv; }

    // ---- pass 2: per-channel union = sum_p e[c,p]/s[p] (smem + shuffles only) ----
    #pragma unroll 2
    for (int c = 0; c < NC; c++) {
        float pv = __half2float(tile[c * TPB + tid]) * inv_s;
        #pragma unroll
        for (int o = 16; o; o >>= 1) pv += __shfl_xor_sync(0xffffffffu, pv, o);
        if (lane == 0) usum[warp * NC + c] = pv;
    }
    __syncthreads();

    // ---- fold block partials into global accumulators ----
    if (tid < NC) {
        float u = 0.f;
        #pragma unroll
        for (int w = 0; w < 8; w++) u += usum[w * NC + tid];
        atomicAdd(&g_union[tid], u);
        float iv = inter_s[tid];
        if (iv != 0.f) atomicAdd(&g_inter[tid], iv);
        float cv = cnt_s[tid];
        if (cv != 0.f) atomicAdd(&g_counts[tid], cv);
    } else if (tid == NC) {
        float n = 0.f, v = 0.f;
        #pragma unroll
        for (int w = 0; w < 8; w++) { n += red[w]; v += red[8 + w]; }
        atomicAdd(&g_nll, n);
        atomicAdd(&g_valid, v);
    }
}

__global__ void seg_final(float* __restrict__ out) {
    __shared__ float sh_d[8], sh_n[8];
    const int tid  = threadIdx.x;   // 256
    const int warp = tid >> 5;
    const int lane = tid & 31;

    float d = 0.f, n = 0.f;
    if (tid < NC) {
        float uni = g_union[tid] + g_counts[tid];
        if (uni > 0.f) {
            d = (2.f * g_inter[tid] + EPSF) / (uni + EPSF);
            n = 1.f;
        }
    }
    #pragma unroll
    for (int o = 16; o; o >>= 1) {
        d += __shfl_xor_sync(0xffffffffu, d, o);
        n += __shfl_xor_sync(0xffffffffu, n, o);
    }
    if (lane == 0) { sh_d[warp] = d; sh_n[warp] = n; }
    __syncthreads();

    if (tid == 0) {
        float dt = 0.f, nt = 0.f;
        #pragma unroll
        for (int w = 0; w < 8; w++) { dt += sh_d[w]; nt += sh_n[w]; }
        float ce   = g_nll / fmaxf(g_valid, 1.f);
        float dice = (nt > 0.f) ? (1.f - dt / fmaxf(nt, 1.f)) : 0.f;
        out[0] = ce + 0.5f * dice;
    }
}

extern "C" void kernel_launch(void* const* d_in, const int* in_sizes, int n_in,
                              void* d_out, int out_size) {
    const float* pred   = (const float*)d_in[0];
    const int*   target = (const int*)d_in[1];
    float*       out    = (float*)d_out;

    const size_t smem = (size_t)NC * TPB * sizeof(__half)
                      + (size_t)(8 * NC + NC + NC + 16) * sizeof(float); // 95008 B
    cudaFuncSetAttribute(seg_main, cudaFuncAttributeMaxDynamicSharedMemorySize, (int)smem);

    seg_zero<<<1, 256>>>();
    seg_main<<<NBLK, TPB, smem>>>(pred, target);
    seg_final<<<1, 256>>>(out);
}

// round 8
// speedup vs baseline: 2.2518x; 2.2478x over previous
#include <cuda_runtime.h>
#include <cuda_fp16.h>

// SegmentationLoss: ce(ignore=255, mean over valid) + 0.5 * dice
// pred [4,172,256,256] f32, target [4,256,256] i32 -> scalar f32
//
// v2: fp8(e4m3) exp stash (44KB tile -> 4 blocks/SM, 32 warps/SM) for 2x MLP,
// explicit 8-wide load batching in pass 1, half2 paired-channel pass 2
// (2 channels per shuffle butterfly). CE path stays fp32-exact.

#define NC   172
#define NCP  (NC/2)             // 86 channel pairs
#define HW   65536
#define NB   4
#define NPIX (NB * HW)          // 262144
#define TPB  256
#define NBLK (NPIX / TPB)       // 1024
#define IGN  255
#define EPSF 1e-7f

__device__ float g_union[NC];
__device__ float g_inter[NC];
__device__ float g_counts[NC];
__device__ float g_nll;
__device__ float g_valid;

__global__ void seg_zero() {
    int t = threadIdx.x;
    if (t < NC) { g_union[t] = 0.f; g_inter[t] = 0.f; g_counts[t] = 0.f; }
    if (t == NC) { g_nll = 0.f; g_valid = 0.f; }
}

__device__ __forceinline__ unsigned short pack_e4m3(float hi, float lo) {
    unsigned short r;
    asm("cvt.rn.satfinite.e4m3x2.f32 %0, %1, %2;" : "=h"(r) : "f"(hi), "f"(lo));
    return r;   // byte1 = e4m3(hi), byte0 = e4m3(lo)
}

__device__ __forceinline__ __half2 unpack_e4m3(unsigned short v) {
    unsigned u;
    asm("cvt.rn.f16x2.e4m3x2 %0, %1;" : "=r"(u) : "h"(v));
    __half2 h;
    *reinterpret_cast<unsigned*>(&h) = u;   // h.lo = byte0, h.hi = byte1
    return h;
}

extern __shared__ unsigned char smem_raw[];

__global__ __launch_bounds__(TPB, 4)
void seg_main(const float* __restrict__ pred, const int* __restrict__ target) {
    // shared layout (51KB/block -> 4 blocks/SM):
    //   tile16 : NCP*TPB u16  (fp8 pair stash, per-thread column, conflict-free)
    //   usum   : 8*NC f32     (per-warp per-channel union partials)
    //   inter_s: NC f32, cnt_s: NC f32 (target-scattered shared atomics)
    //   red    : 16 f32
    unsigned short* tile16 = (unsigned short*)smem_raw;
    float* usum    = (float*)(smem_raw + (size_t)NCP * TPB * sizeof(unsigned short));
    float* inter_s = usum + 8 * NC;
    float* cnt_s   = inter_s + NC;
    float* red     = cnt_s + NC;

    const int tid  = threadIdx.x;
    const int warp = tid >> 5;
    const int lane = tid & 31;

    for (int i = tid; i < NC; i += TPB) { inter_s[i] = 0.f; cnt_s[i] = 0.f; }
    __syncthreads();

    const int pix0 = blockIdx.x * TPB;          // 65536 % 256 == 0 -> never crosses batch
    const int b    = pix0 >> 16;
    const int hw   = pix0 & (HW - 1);
    const float* ptr = pred + (size_t)b * NC * HW + hw + tid;

    const int  tgt   = target[pix0 + tid];
    const bool valid = (tgt != IGN);

    // ---- pass 1: stream DRAM in batches of 8, exp, sum, stash fp8 pairs ----
    float s = 0.f, xt = 0.f;
    #pragma unroll 1
    for (int i = 0; i < 21; i++) {              // 21*8 = 168 channels
        float x[8];
        #pragma unroll
        for (int j = 0; j < 8; j++) x[j] = __ldg(ptr + (size_t)j * HW);
        ptr += (size_t)8 * HW;
        float e[8];
        #pragma unroll
        for (int j = 0; j < 8; j++) {
            e[j] = __expf(x[j]);
            s += e[j];
            if (i * 8 + j == tgt) xt = x[j];
        }
        const int cp = i * 4;
        #pragma unroll
        for (int jp = 0; jp < 4; jp++)
            tile16[(cp + jp) * TPB + tid] = pack_e4m3(e[2*jp+1], e[2*jp]);
    }
    {   // tail: channels 168..171
        float x[4];
        #pragma unroll
        for (int j = 0; j < 4; j++) x[j] = __ldg(ptr + (size_t)j * HW);
        float e[4];
        #pragma unroll
        for (int j = 0; j < 4; j++) {
            e[j] = __expf(x[j]);
            s += e[j];
            if (168 + j == tgt) xt = x[j];
        }
        tile16[84 * TPB + tid] = pack_e4m3(e[1], e[0]);
        tile16[85 * TPB + tid] = pack_e4m3(e[3], e[2]);
    }

    const float inv_s = 1.f / s;
    float nll = valid ? (__logf(s) - xt) : 0.f;
    float vv  = valid ? 1.f : 0.f;

    if (valid) {
        float pt = __expf(xt) * inv_s;          // p at target, fp32-exact path
        atomicAdd(&inter_s[tgt], pt);
        atomicAdd(&cnt_s[tgt], 1.f);
    }

    #pragma unroll
    for (int o = 16; o; o >>= 1) {
        nll += __shfl_xor_sync(0xffffffffu, nll, o);
        vv  += __shfl_xor_sync(0xffffffffu, vv,  o);
    }
    if (lane == 0) { red[warp] = nll; red[8 + warp] = vv; }

    // ---- pass 2: per-channel union via half2 (2 channels per butterfly) ----
    const __half2 inv2 = __float2half2_rn(inv_s);
    #pragma unroll 2
    for (int cp = 0; cp < NCP; cp++) {
        __half2 p2 = __hmul2(unpack_e4m3(tile16[cp * TPB + tid]), inv2);
        #pragma unroll
        for (int o = 16; o; o >>= 1)
            p2 = __hadd2(p2, __shfl_xor_sync(0xffffffffu, p2, o));
        if (lane == 0) {
            float2 f = __half22float2(p2);
            usum[warp * NC + 2*cp]     = f.x;   // low half = even channel
            usum[warp * NC + 2*cp + 1] = f.y;
        }
    }
    __syncthreads();

    // ---- fold block partials into global accumulators ----
    if (tid < NC) {
        float u = 0.f;
        #pragma unroll
        for (int w = 0; w < 8; w++) u += usum[w * NC + tid];
        atomicAdd(&g_union[tid], u);
        float iv = inter_s[tid];
        if (iv != 0.f) atomicAdd(&g_inter[tid], iv);
        float cv = cnt_s[tid];
        if (cv != 0.f) atomicAdd(&g_counts[tid], cv);
    } else if (tid == NC) {
        float n = 0.f, v = 0.f;
        #pragma unroll
        for (int w = 0; w < 8; w++) { n += red[w]; v += red[8 + w]; }
        atomicAdd(&g_nll, n);
        atomicAdd(&g_valid, v);
    }
}

__global__ void seg_final(float* __restrict__ out) {
    __shared__ float sh_d[8], sh_n[8];
    const int tid  = threadIdx.x;   // 256
    const int warp = tid >> 5;
    const int lane = tid & 31;

    float d = 0.f, n = 0.f;
    if (tid < NC) {
        float uni = g_union[tid] + g_counts[tid];
        if (uni > 0.f) {
            d = (2.f * g_inter[tid] + EPSF) / (uni + EPSF);
            n = 1.f;
        }
    }
    #pragma unroll
    for (int o = 16; o; o >>= 1) {
        d += __shfl_xor_sync(0xffffffffu, d, o);
        n += __shfl_xor_sync(0xffffffffu, n, o);
    }
    if (lane == 0) { sh_d[warp] = d; sh_n[warp] = n; }
    __syncthreads();

    if (tid == 0) {
        float dt = 0.f, nt = 0.f;
        #pragma unroll
        for (int w = 0; w < 8; w++) { dt += sh_d[w]; nt += sh_n[w]; }
        float ce   = g_nll / fmaxf(g_valid, 1.f);
        float dice = (nt > 0.f) ? (1.f - dt / fmaxf(nt, 1.f)) : 0.f;
        out[0] = ce + 0.5f * dice;
    }
}

extern "C" void kernel_launch(void* const* d_in, const int* in_sizes, int n_in,
                              void* d_out, int out_size) {
    const float* pred   = (const float*)d_in[0];
    const int*   target = (const int*)d_in[1];
    float*       out    = (float*)d_out;

    const size_t smem = (size_t)NCP * TPB * sizeof(unsigned short)
                      + (size_t)(8 * NC + NC + NC + 16) * sizeof(float); // 50,976 B
    cudaFuncSetAttribute(seg_main, cudaFuncAttributeMaxDynamicSharedMemorySize, (int)smem);

    seg_zero<<<1, 256>>>();
    seg_main<<<NBLK, TPB, smem>>>(pred, target);
    seg_final<<<1, 256>>>(out);
}